// round 8
// baseline (speedup 1.0000x reference)
#include <cuda_runtime.h>
#include <cuda_fp16.h>
#include <cuda_fp8.h>
#include <cstdint>

// Problem constants (fixed shapes)
#define BQ  16
#define CC  256
#define HH  48
#define WW  48
#define NN  (HH*WW)      // 2304
#define KNN 8
#define KB  16           // per-thread candidate buffer (2 threads/row -> 32)
#define NCAND (2*KB)     // 32 candidates per row == warp size
#define TILE 128
#define NTILES (NN/TILE) // 18
#define NCHUNK (NTILES*4)
#define SCP 132          // Sc row stride (floats)

// gram smem layout (bytes); chunk row = 64 e4m3 + 16 pad = 80 B (16B aligned)
#define CRW8   80
#define CHUNK8 (128*CRW8)          // 10240
#define SMB_A0 0
#define SMB_A1 10240
#define SMB_B0 20480
#define SMB_B1 30720
#define SMB_SC 40960               // float[128][132] = 67584
#define SMB_SQ 108544              // float[128]
#define SMB_TOT (108544 + 512)

// Scratch (device globals; no allocation allowed)
__device__ __align__(256) float   g_nodesT[BQ * NN * CC];  // fp32 features [B][N][C]
__device__ __align__(256) uint8_t g_fp8[BQ * NN * CC];     // e4m3 copy for filter GEMM
__device__ __align__(256) float   g_sq[BQ * NN];           // squared norms
__device__ __align__(256) int     g_cand[BQ * NN * NCAND]; // filtered candidates

__device__ __forceinline__ uint32_t smem_u32(const void* p) {
    uint32_t a;
    asm("{ .reg .u64 t; cvta.to.shared.u64 t, %1; cvt.u32.u64 %0, t; }"
        : "=r"(a) : "l"(p));
    return a;
}
#define CP_ASYNC16(dst, src) \
    asm volatile("cp.async.cg.shared.global [%0], [%1], 16;" :: "r"(dst), "l"(src))
#define CP_COMMIT() asm volatile("cp.async.commit_group;" ::: "memory")
#define CP_WAIT(n)  asm volatile("cp.async.wait_group %0;" :: "n"(n) : "memory")

#define LDSM_X4(r0, r1, r2, r3, addr) \
    asm volatile("ldmatrix.sync.aligned.m8n8.x4.shared.b16 {%0,%1,%2,%3}, [%4];" \
        : "=r"(r0), "=r"(r1), "=r"(r2), "=r"(r3) : "r"(addr))

#define QMMA32(acc, a0, a1, a2, a3, b0, b1) \
    asm volatile("mma.sync.aligned.m16n8k32.row.col.f32.e4m3.e4m3.f32 " \
        "{%0,%1,%2,%3}, {%4,%5,%6,%7}, {%8,%9}, {%0,%1,%2,%3};" \
        : "+f"((acc)[0]), "+f"((acc)[1]), "+f"((acc)[2]), "+f"((acc)[3]) \
        : "r"(a0), "r"(a1), "r"(a2), "r"(a3), "r"(b0), "r"(b1))

// ---------------------------------------------------------------------------
// Kernel 1: transpose F[b][c][n] -> nodesT[b][n][c] (fp32 + e4m3 copies)
// ---------------------------------------------------------------------------
__global__ void k_transpose(const float* __restrict__ F) {
    __shared__ float t[32][33];
    int b  = blockIdx.z;
    int n0 = blockIdx.x * 32;
    int c0 = blockIdx.y * 32;
    const float* Fb = F + (size_t)b * CC * NN;
    int tx = threadIdx.x, ty = threadIdx.y;  // 32 x 8
#pragma unroll
    for (int i = 0; i < 32; i += 8)
        t[ty + i][tx] = Fb[(size_t)(c0 + ty + i) * NN + n0 + tx];
    __syncthreads();
    float* out = g_nodesT + (size_t)b * NN * CC;
    uint8_t* out8 = g_fp8 + (size_t)b * NN * CC;
#pragma unroll
    for (int i = 0; i < 32; i += 8) {
        float v = t[tx][ty + i];
        size_t o = (size_t)(n0 + ty + i) * CC + c0 + tx;
        out[o]  = v;
        __nv_fp8_e4m3 q(v);
        out8[o] = *(uint8_t*)&q;
    }
}

// ---------------------------------------------------------------------------
// Kernel 2: squared norms sq[b][n]
// ---------------------------------------------------------------------------
__global__ void k_sq(const float* __restrict__ F) {
    int gid = blockIdx.x * blockDim.x + threadIdx.x;
    if (gid >= BQ * NN) return;
    int b = gid / NN, n = gid % NN;
    const float* Fb = F + (size_t)b * CC * NN + n;
    float s = 0.f;
#pragma unroll 8
    for (int c = 0; c < CC; ++c) {
        float v = Fb[(size_t)c * NN];
        s += v * v;
    }
    g_sq[gid] = s;
}

// ---------------------------------------------------------------------------
// Kernel 3: e4m3 mma.m16n8k32 (f32 acc) Gram + per-half top-16 filter.
// CTA = (b, 128-row stripe); 256 thr = 8 warps (4 wm x 2 wn); warp tile 32x64.
// A and B in 128x64-elem (64 B) K-chunks, double-buffered via cp.async.
// Fragments via ldmatrix.b16 (byte layout identical to fp16 k16 path).
// smem ~106 KB -> 2 CTAs/SM.
// ---------------------------------------------------------------------------
__global__ __launch_bounds__(256, 2) void k_gram_topk_mma() {
    extern __shared__ unsigned char smraw[];
    const uint32_t smb = smem_u32(smraw);
    float* Sc  = (float*)(smraw + SMB_SC);   // [128][132]
    float* sqs = (float*)(smraw + SMB_SQ);

    const int b   = blockIdx.y;
    const int i0  = blockIdx.x * TILE;
    const int tid = threadIdx.x;
    const int wid  = tid >> 5;
    const int lane = tid & 31;
    const int wm = wid >> 1;       // 0..3
    const int wn = wid & 1;        // 0..1
    const int grp = lane >> 2;     // 0..7
    const int tig = lane & 3;      // 0..3
    const int quad = lane >> 3;    // 0..3
    const int wi   = lane & 7;
    const uint8_t* Qb = g_fp8 + (size_t)b * NN * CC;

    // chunk copy geometry: 2 threads per row, 32B halves
    const int crow  = tid >> 1;
    const int chalf = tid & 1;

    // ldmatrix per-lane offsets (within a chunk buffer)
    uint32_t aoff[2], boff[4];
#pragma unroll
    for (int mt = 0; mt < 2; ++mt) {
        int row = wm * 32 + mt * 16 + wi + 8 * (quad & 1);
        aoff[mt] = row * CRW8 + (quad >> 1) * 16;
    }
#pragma unroll
    for (int p = 0; p < 4; ++p) {
        int row = wn * 64 + p * 16 + wi + 8 * (quad >> 1);
        boff[p] = row * CRW8 + (quad & 1) * 16;
    }

    // per-thread top-16 ([0]=worst)
    float ts[KB];
    int   ti[KB];
#pragma unroll
    for (int k = 0; k < KB; ++k) { ts[k] = 3.0e38f; ti[k] = 0; }
    const int srow  = tid >> 1;
    const int shalf = tid & 1;
    const int ig    = i0 + srow;

    // issue chunk q (A chunk + B chunk -> buffer q&1), one commit group
    auto issue = [&](int q) {
        const int jt = q >> 2, c = q & 3, buf = q & 1;
        const char* asrc =
            (const char*)(Qb + (size_t)(i0 + crow) * CC + c * 64 + chalf * 32);
        const char* bsrc =
            (const char*)(Qb + (size_t)(jt * TILE + crow) * CC + c * 64 + chalf * 32);
        uint32_t adst = smb + (buf ? SMB_A1 : SMB_A0) + crow * CRW8 + chalf * 32;
        uint32_t bdst = smb + (buf ? SMB_B1 : SMB_B0) + crow * CRW8 + chalf * 32;
#pragma unroll
        for (int i = 0; i < 2; ++i) {
            CP_ASYNC16(adst + i * 16, asrc + i * 16);
            CP_ASYNC16(bdst + i * 16, bsrc + i * 16);
        }
        CP_COMMIT();
    };

    issue(0);
    int q = 0;

    for (int jt = 0; jt < NTILES; ++jt) {
        const int j0 = jt * TILE;

        float acc[2][8][4];
#pragma unroll
        for (int mt = 0; mt < 2; ++mt)
#pragma unroll
            for (int nt = 0; nt < 8; ++nt)
#pragma unroll
                for (int u = 0; u < 4; ++u) acc[mt][nt][u] = 0.f;

        for (int c = 0; c < 4; ++c, ++q) {
            if (q + 1 < NCHUNK) { issue(q + 1); CP_WAIT(1); }
            else                {                CP_WAIT(0); }
            __syncthreads();   // chunk q visible; prior scans/buffer reads done

            if (c == 0 && tid < TILE) sqs[tid] = g_sq[b * NN + j0 + tid];

            const uint32_t abase = smb + ((q & 1) ? SMB_A1 : SMB_A0);
            const uint32_t bbase = smb + ((q & 1) ? SMB_B1 : SMB_B0);
#pragma unroll
            for (int ks = 0; ks < 2; ++ks) {        // two k32 steps per chunk
                const int ko = ks * 32;
                uint32_t a[2][4];
#pragma unroll
                for (int mt = 0; mt < 2; ++mt)
                    LDSM_X4(a[mt][0], a[mt][1], a[mt][2], a[mt][3],
                            abase + aoff[mt] + ko);
                uint32_t bb[4][4];
#pragma unroll
                for (int p = 0; p < 4; ++p)
                    LDSM_X4(bb[p][0], bb[p][1], bb[p][2], bb[p][3],
                            bbase + boff[p] + ko);
#pragma unroll
                for (int mt = 0; mt < 2; ++mt)
#pragma unroll
                    for (int p = 0; p < 4; ++p) {
                        QMMA32(acc[mt][2*p],
                               a[mt][0], a[mt][1], a[mt][2], a[mt][3],
                               bb[p][0], bb[p][1]);
                        QMMA32(acc[mt][2*p+1],
                               a[mt][0], a[mt][1], a[mt][2], a[mt][3],
                               bb[p][2], bb[p][3]);
                    }
            }
            __syncthreads();   // all warps done with buffer q&1
        }

        // stage scores to smem
#pragma unroll
        for (int mt = 0; mt < 2; ++mt) {
            const int r0 = wm * 32 + mt * 16 + grp;
#pragma unroll
            for (int nt = 0; nt < 8; ++nt) {
                const int c0 = wn * 64 + nt * 8 + 2 * tig;
                *(float2*)&Sc[r0 * SCP + c0] =
                    make_float2(acc[mt][nt][0], acc[mt][nt][1]);
                *(float2*)&Sc[(r0 + 8) * SCP + c0] =
                    make_float2(acc[mt][nt][2], acc[mt][nt][3]);
            }
        }
        __syncthreads();

        // scan: key = sq[j] - 2*dot (sq[i] constant per row)
        const float* srcrow = &Sc[srow * SCP + shalf * 64];
        const float* sqrow  = &sqs[shalf * 64];
        const int jbase = j0 + shalf * 64;
#pragma unroll 4
        for (int s = 0; s < 64; ++s) {
            int j = jbase + s;
            float key = sqrow[s] - 2.0f * srcrow[s];
            if (j != ig && key < ts[0]) {
                ts[0] = key; ti[0] = j;
#pragma unroll
                for (int t2 = 0; t2 < KB - 1; ++t2)
                    if (ts[t2] < ts[t2 + 1]) {
                        float tf = ts[t2]; ts[t2] = ts[t2 + 1]; ts[t2 + 1] = tf;
                        int tn = ti[t2]; ti[t2] = ti[t2 + 1]; ti[t2 + 1] = tn;
                    }
            }
        }
        // next tile's first chunk sync orders the scan before Sc/sqs overwrite
    }

    // write 16 candidates per half (rescore picks exact top-8)
    {
        int base = ((b * NN + ig) * 2 + shalf) * KB;
#pragma unroll
        for (int k = 0; k < KB; ++k) g_cand[base + k] = ti[k];
    }
}

// ---------------------------------------------------------------------------
// Kernel 4: fused exact rescore (32 cand -> top-8) + aggregation + LayerNorm.
// 4-way unrolled rescore: 4 concurrent dot+reduction chains for MLP/ILP.
// ---------------------------------------------------------------------------
__global__ __launch_bounds__(256) void k_refine(const float* __restrict__ gamma,
                                                const float* __restrict__ beta,
                                                float* __restrict__ out) {
    const int b    = blockIdx.y;
    const int wid  = threadIdx.x >> 5;
    const int lane = threadIdx.x & 31;
    const int n0   = blockIdx.x * 8;
    const int n    = n0 + wid;
    const int h = n / WW, w = n % WW;
    const float* Nb = g_nodesT + (size_t)b * NN * CC;

    const float* xi = Nb + (size_t)n * CC + lane * 8;
    float4 x0 = *(const float4*)xi;
    float4 x1 = *(const float4*)(xi + 4);

    // ---- exact rescore of 32 candidates, 4 at a time ----
    int cand = g_cand[(b * NN + n) * NCAND + lane];
    float mykey = 3.0e38f;
    int   myidx = cand;
#pragma unroll
    for (int k0 = 0; k0 < NCAND; k0 += 4) {
        float p0, p1, p2, p3;
        {
            int j0 = __shfl_sync(0xffffffffu, cand, k0);
            int j1 = __shfl_sync(0xffffffffu, cand, k0 + 1);
            int j2 = __shfl_sync(0xffffffffu, cand, k0 + 2);
            int j3 = __shfl_sync(0xffffffffu, cand, k0 + 3);
            const float* r0p = Nb + (size_t)j0 * CC + lane * 8;
            const float* r1p = Nb + (size_t)j1 * CC + lane * 8;
            const float* r2p = Nb + (size_t)j2 * CC + lane * 8;
            const float* r3p = Nb + (size_t)j3 * CC + lane * 8;
            float4 a0 = *(const float4*)r0p, a1 = *(const float4*)(r0p + 4);
            float4 b0 = *(const float4*)r1p, b1 = *(const float4*)(r1p + 4);
            float4 c0 = *(const float4*)r2p, c1 = *(const float4*)(r2p + 4);
            float4 d0 = *(const float4*)r3p, d1 = *(const float4*)(r3p + 4);
            p0 = x0.x*a0.x + x0.y*a0.y + x0.z*a0.z + x0.w*a0.w
               + x1.x*a1.x + x1.y*a1.y + x1.z*a1.z + x1.w*a1.w;
            p1 = x0.x*b0.x + x0.y*b0.y + x0.z*b0.z + x0.w*b0.w
               + x1.x*b1.x + x1.y*b1.y + x1.z*b1.z + x1.w*b1.w;
            p2 = x0.x*c0.x + x0.y*c0.y + x0.z*c0.z + x0.w*c0.w
               + x1.x*c1.x + x1.y*c1.y + x1.z*c1.z + x1.w*c1.w;
            p3 = x0.x*d0.x + x0.y*d0.y + x0.z*d0.z + x0.w*d0.w
               + x1.x*d1.x + x1.y*d1.y + x1.z*d1.z + x1.w*d1.w;
#pragma unroll
            for (int o = 16; o > 0; o >>= 1) {
                p0 += __shfl_xor_sync(0xffffffffu, p0, o);
                p1 += __shfl_xor_sync(0xffffffffu, p1, o);
                p2 += __shfl_xor_sync(0xffffffffu, p2, o);
                p3 += __shfl_xor_sync(0xffffffffu, p3, o);
            }
            float sq0 = g_sq[b * NN + j0], sq1 = g_sq[b * NN + j1];
            float sq2 = g_sq[b * NN + j2], sq3 = g_sq[b * NN + j3];
            if (lane == k0)     mykey = sq0 - 2.0f * p0;
            if (lane == k0 + 1) mykey = sq1 - 2.0f * p1;
            if (lane == k0 + 2) mykey = sq2 - 2.0f * p2;
            if (lane == k0 + 3) mykey = sq3 - 2.0f * p3;
        }
    }

    // ---- select 8 smallest; indices broadcast to all lanes ----
    int knn_j[KNN];
#pragma unroll
    for (int t = 0; t < KNN; ++t) {
        float v = mykey;
#pragma unroll
        for (int o = 16; o > 0; o >>= 1) v = fminf(v, __shfl_xor_sync(0xffffffffu, v, o));
        unsigned m = __ballot_sync(0xffffffffu, mykey == v);
        int src = __ffs(m) - 1;
        knn_j[t] = __shfl_sync(0xffffffffu, myidx, src);
        if (lane == src) mykey = 3.0e38f;
    }

    // ---- aggregate: 4-neighborhood grid + 8 knn, mean; residual ----
    float acc[8];
#pragma unroll
    for (int r = 0; r < 8; ++r) acc[r] = 0.f;
    int cnt = KNN;
#pragma unroll
    for (int t = 0; t < KNN; ++t) {
        const float* p = Nb + (size_t)knn_j[t] * CC + lane * 8;
        float4 y0 = *(const float4*)p;
        float4 y1 = *(const float4*)(p + 4);
        acc[0] += y0.x; acc[1] += y0.y; acc[2] += y0.z; acc[3] += y0.w;
        acc[4] += y1.x; acc[5] += y1.y; acc[6] += y1.z; acc[7] += y1.w;
    }
    if (w > 0)      { const float* p = Nb + (size_t)(n - 1)  * CC + lane * 8;
        float4 y0 = *(const float4*)p; float4 y1 = *(const float4*)(p + 4);
        acc[0]+=y0.x; acc[1]+=y0.y; acc[2]+=y0.z; acc[3]+=y0.w;
        acc[4]+=y1.x; acc[5]+=y1.y; acc[6]+=y1.z; acc[7]+=y1.w; cnt++; }
    if (w < WW - 1) { const float* p = Nb + (size_t)(n + 1)  * CC + lane * 8;
        float4 y0 = *(const float4*)p; float4 y1 = *(const float4*)(p + 4);
        acc[0]+=y0.x; acc[1]+=y0.y; acc[2]+=y0.z; acc[3]+=y0.w;
        acc[4]+=y1.x; acc[5]+=y1.y; acc[6]+=y1.z; acc[7]+=y1.w; cnt++; }
    if (h > 0)      { const float* p = Nb + (size_t)(n - WW) * CC + lane * 8;
        float4 y0 = *(const float4*)p; float4 y1 = *(const float4*)(p + 4);
        acc[0]+=y0.x; acc[1]+=y0.y; acc[2]+=y0.z; acc[3]+=y0.w;
        acc[4]+=y1.x; acc[5]+=y1.y; acc[6]+=y1.z; acc[7]+=y1.w; cnt++; }
    if (h < HH - 1) { const float* p = Nb + (size_t)(n + WW) * CC + lane * 8;
        float4 y0 = *(const float4*)p; float4 y1 = *(const float4*)(p + 4);
        acc[0]+=y0.x; acc[1]+=y0.y; acc[2]+=y0.z; acc[3]+=y0.w;
        acc[4]+=y1.x; acc[5]+=y1.y; acc[6]+=y1.z; acc[7]+=y1.w; cnt++; }

    const float inv = 1.0f / (float)cnt;
    float xv[8] = {x0.x, x0.y, x0.z, x0.w, x1.x, x1.y, x1.z, x1.w};
    float y[8];
#pragma unroll
    for (int r = 0; r < 8; ++r) y[r] = acc[r] * inv + xv[r];

    // ---- LayerNorm over channels ----
    float s = 0.f;
#pragma unroll
    for (int r = 0; r < 8; ++r) s += y[r];
#pragma unroll
    for (int o = 16; o > 0; o >>= 1) s += __shfl_xor_sync(0xffffffffu, s, o);
    const float mu = s * (1.0f / CC);
    float v = 0.f;
#pragma unroll
    for (int r = 0; r < 8; ++r) { float d = y[r] - mu; v += d * d; }
#pragma unroll
    for (int o = 16; o > 0; o >>= 1) v += __shfl_xor_sync(0xffffffffu, v, o);
    const float rs = rsqrtf(v * (1.0f / CC) + 1e-5f);

    __shared__ float st[8][CC];
#pragma unroll
    for (int r = 0; r < 8; ++r) {
        int c = lane * 8 + r;
        st[wid][c] = (y[r] - mu) * rs * gamma[c] + beta[c];
    }
    __syncthreads();

    const int c = threadIdx.x;
    float4 v0 = make_float4(st[0][c], st[1][c], st[2][c], st[3][c]);
    float4 v1 = make_float4(st[4][c], st[5][c], st[6][c], st[7][c]);
    size_t o = (size_t)b * CC * NN + (size_t)c * NN + n0;
    *(float4*)&out[o]     = v0;
    *(float4*)&out[o + 4] = v1;
}

// ---------------------------------------------------------------------------
extern "C" void kernel_launch(void* const* d_in, const int* in_sizes, int n_in,
                              void* d_out, int out_size) {
    const float* F     = (const float*)d_in[0];
    const float* gamma = (const float*)d_in[1];
    const float* beta  = (const float*)d_in[2];
    float* out = (float*)d_out;
    (void)in_sizes; (void)n_in; (void)out_size;

    k_transpose<<<dim3(NN / 32, CC / 32, BQ), dim3(32, 8)>>>(F);
    k_sq<<<(BQ * NN + 255) / 256, 256>>>(F);

    cudaFuncSetAttribute(k_gram_topk_mma,
                         cudaFuncAttributeMaxDynamicSharedMemorySize, SMB_TOT);
    k_gram_topk_mma<<<dim3(NTILES, BQ), 256, SMB_TOT>>>();

    k_refine<<<dim3(NN / 8, BQ), 256>>>(gamma, beta, out);
}

// round 9
// speedup vs baseline: 1.0166x; 1.0166x over previous
#include <cuda_runtime.h>
#include <cuda_fp16.h>
#include <cstdint>

// Problem constants (fixed shapes)
#define BQ  16
#define CC  256
#define HH  48
#define WW  48
#define NN  (HH*WW)      // 2304
#define KNN 8
#define KB  12           // per-(tile,half) candidate list length
#define NSLOT 36         // 18 stripes x 2 halves
#define NLIST (NSLOT*KB) // 432 packed candidates per node
#define NCAND 24         // merged candidates that get exact rescore
#define TILE 128
#define NTILES (NN/TILE) // 18
#define NPAIR  171       // NTILES*(NTILES+1)/2

// gram smem layout (bytes); fp16 chunk row = 64 fp16 (128B) + 16 pad = 144
#define CRW    144
#define SMB_A0 0
#define SMB_A1 18432
#define SMB_B0 36864
#define SMB_B1 55296
#define SMB_SC 73728               // half2[128][65] = 33280
#define SCH2   65
#define SMB_SQI 107008             // float[128]
#define SMB_SQJ 107520             // float[128]
#define SMB_TOT 108032

// Scratch (device globals; no allocation allowed)
__device__ __align__(256) float    g_nodesT[BQ * NN * CC];  // fp32 features [B][N][C]
__device__ __align__(256) __half   g_half[BQ * NN * CC];    // fp16 copy for filter GEMM
__device__ __align__(256) float    g_sq[BQ * NN];           // squared norms
__device__ __align__(256) uint32_t g_ps[(size_t)BQ * NN * NLIST]; // packed cand lists

__device__ __forceinline__ uint32_t smem_u32(const void* p) {
    uint32_t a;
    asm("{ .reg .u64 t; cvta.to.shared.u64 t, %1; cvt.u32.u64 %0, t; }"
        : "=r"(a) : "l"(p));
    return a;
}
#define CP_ASYNC16(dst, src) \
    asm volatile("cp.async.cg.shared.global [%0], [%1], 16;" :: "r"(dst), "l"(src))
#define CP_COMMIT() asm volatile("cp.async.commit_group;" ::: "memory")
#define CP_WAIT(n)  asm volatile("cp.async.wait_group %0;" :: "n"(n) : "memory")

#define LDSM_X4(r0, r1, r2, r3, addr) \
    asm volatile("ldmatrix.sync.aligned.m8n8.x4.shared.b16 {%0,%1,%2,%3}, [%4];" \
        : "=r"(r0), "=r"(r1), "=r"(r2), "=r"(r3) : "r"(addr))

#define HMMA16(acc0, acc1, a0, a1, a2, a3, b0, b1) \
    asm volatile("mma.sync.aligned.m16n8k16.row.col.f16.f16.f16.f16 " \
        "{%0,%1}, {%2,%3,%4,%5}, {%6,%7}, {%0,%1};" \
        : "+r"(acc0), "+r"(acc1) \
        : "r"(a0), "r"(a1), "r"(a2), "r"(a3), "r"(b0), "r"(b1))

// pack fp32 key -> monotone fp16 bits (hi) | node idx (lo); uint32 asc == key asc
__device__ __forceinline__ uint32_t packkey(float key, int idx) {
    unsigned short h = __half_as_ushort(__float2half_rn(key));
    h = (unsigned short)(h ^ ((h & 0x8000) ? 0xFFFFu : 0x8000u));
    return ((uint32_t)h << 16) | (uint32_t)(idx & 0xFFFF);
}

// insertion update for a top-KB list, [0]=worst
#define LIST_INSERT(ts, ti, key, idx) do { \
    if ((key) < (ts)[0]) { \
        (ts)[0] = (key); (ti)[0] = (idx); \
        _Pragma("unroll") \
        for (int _t = 0; _t < KB - 1; ++_t) \
            if ((ts)[_t] < (ts)[_t + 1]) { \
                float _f = (ts)[_t]; (ts)[_t] = (ts)[_t+1]; (ts)[_t+1] = _f; \
                int _n = (ti)[_t]; (ti)[_t] = (ti)[_t+1]; (ti)[_t+1] = _n; \
            } \
    } \
} while (0)

// ---------------------------------------------------------------------------
// Kernel 1: transpose F[b][c][n] -> nodesT[b][n][c] (fp32 + fp16 copies)
// ---------------------------------------------------------------------------
__global__ void k_transpose(const float* __restrict__ F) {
    __shared__ float t[32][33];
    int b  = blockIdx.z;
    int n0 = blockIdx.x * 32;
    int c0 = blockIdx.y * 32;
    const float* Fb = F + (size_t)b * CC * NN;
    int tx = threadIdx.x, ty = threadIdx.y;  // 32 x 8
#pragma unroll
    for (int i = 0; i < 32; i += 8)
        t[ty + i][tx] = Fb[(size_t)(c0 + ty + i) * NN + n0 + tx];
    __syncthreads();
    float* out = g_nodesT + (size_t)b * NN * CC;
    __half* outh = g_half + (size_t)b * NN * CC;
#pragma unroll
    for (int i = 0; i < 32; i += 8) {
        float v = t[tx][ty + i];
        size_t o = (size_t)(n0 + ty + i) * CC + c0 + tx;
        out[o]  = v;
        outh[o] = __float2half(v);
    }
}

// ---------------------------------------------------------------------------
// Kernel 2: squared norms from g_nodesT (coalesced; warp per node)
// ---------------------------------------------------------------------------
__global__ void k_sq() {
    const int wid  = threadIdx.x >> 5;
    const int lane = threadIdx.x & 31;
    const int n = blockIdx.x * 8 + wid;
    const int b = blockIdx.y;
    const float* p = g_nodesT + (size_t)(b * NN + n) * CC + lane * 8;
    float4 a = *(const float4*)p;
    float4 c = *(const float4*)(p + 4);
    float s = a.x*a.x + a.y*a.y + a.z*a.z + a.w*a.w
            + c.x*c.x + c.y*c.y + c.z*c.z + c.w*c.w;
#pragma unroll
    for (int o = 16; o > 0; o >>= 1) s += __shfl_xor_sync(0xffffffffu, s, o);
    if (lane == 0) g_sq[b * NN + n] = s;
}

// ---------------------------------------------------------------------------
// Kernel 3: symmetric fp16 Gram — one CTA per tile-pair (it <= jt).
// MMA core identical to R7 (fp16 in / fp16 acc, cp.async double-buffered).
// Scan BOTH ways: rows -> candidates for stripe it nodes (slot 2*jt+half),
// cols -> candidates for stripe jt nodes (slot 2*it+half; skipped on diag).
// Each (node, slot) written exactly once. Packed (mono-fp16 key | idx16).
// ---------------------------------------------------------------------------
__global__ __launch_bounds__(256, 2) void k_gram_sym() {
    extern __shared__ unsigned char smraw[];
    const uint32_t smb = smem_u32(smraw);
    uint32_t* Scw = (uint32_t*)(smraw + SMB_SC);  // half2[128][65]
    float*    sqi = (float*)(smraw + SMB_SQI);
    float*    sqj = (float*)(smraw + SMB_SQJ);

    const int b = blockIdx.y;
    // map linear pair index -> (it, jt), it <= jt
    int tlin = blockIdx.x, it = 0;
    while (tlin >= NTILES - it) { tlin -= NTILES - it; ++it; }
    const int jt = it + tlin;
    const int i0 = it * TILE, j0 = jt * TILE;

    const int tid = threadIdx.x;
    const int wid  = tid >> 5;
    const int lane = tid & 31;
    const int wm = wid >> 1;       // 0..3
    const int wn = wid & 1;        // 0..1
    const int grp = lane >> 2;     // 0..7
    const int tig = lane & 3;      // 0..3
    const int quad = lane >> 3;    // 0..3
    const int wi   = lane & 7;
    const __half* Hb = g_half + (size_t)b * NN * CC;

    // chunk copy geometry: 2 threads per row, 64B halves
    const int crow  = tid >> 1;
    const int chalf = tid & 1;

    // ldmatrix per-lane offsets (within a chunk buffer)
    uint32_t aoff[2], boff[4];
#pragma unroll
    for (int mt = 0; mt < 2; ++mt) {
        int row = wm * 32 + mt * 16 + wi + 8 * (quad & 1);
        aoff[mt] = row * CRW + (quad >> 1) * 16;
    }
#pragma unroll
    for (int p = 0; p < 4; ++p) {
        int row = wn * 64 + p * 16 + wi + 8 * (quad >> 1);
        boff[p] = row * CRW + (quad & 1) * 16;
    }

    // issue chunk q (A from stripe it, B from stripe jt -> buffer q&1)
    auto issue = [&](int q) {
        const int c = q, buf = q & 1;
        const char* asrc =
            (const char*)(Hb + (size_t)(i0 + crow) * CC + c * 64 + chalf * 32);
        const char* bsrc =
            (const char*)(Hb + (size_t)(j0 + crow) * CC + c * 64 + chalf * 32);
        uint32_t adst = smb + (buf ? SMB_A1 : SMB_A0) + crow * CRW + chalf * 64;
        uint32_t bdst = smb + (buf ? SMB_B1 : SMB_B0) + crow * CRW + chalf * 64;
#pragma unroll
        for (int i = 0; i < 4; ++i) {
            CP_ASYNC16(adst + i * 16, asrc + i * 16);
            CP_ASYNC16(bdst + i * 16, bsrc + i * 16);
        }
        CP_COMMIT();
    };

    issue(0);

    uint32_t acc[2][8][2];
#pragma unroll
    for (int mt = 0; mt < 2; ++mt)
#pragma unroll
        for (int nt = 0; nt < 8; ++nt)
            acc[mt][nt][0] = acc[mt][nt][1] = 0u;

    for (int q = 0; q < 4; ++q) {
        if (q + 1 < 4) { issue(q + 1); CP_WAIT(1); }
        else           {               CP_WAIT(0); }
        __syncthreads();

        const uint32_t abase = smb + ((q & 1) ? SMB_A1 : SMB_A0);
        const uint32_t bbase = smb + ((q & 1) ? SMB_B1 : SMB_B0);
#pragma unroll
        for (int ks = 0; ks < 4; ++ks) {
            const int ko = ks * 32;
            uint32_t a[2][4];
#pragma unroll
            for (int mt = 0; mt < 2; ++mt)
                LDSM_X4(a[mt][0], a[mt][1], a[mt][2], a[mt][3],
                        abase + aoff[mt] + ko);
            uint32_t bb[4][4];
#pragma unroll
            for (int p = 0; p < 4; ++p)
                LDSM_X4(bb[p][0], bb[p][1], bb[p][2], bb[p][3],
                        bbase + boff[p] + ko);
#pragma unroll
            for (int mt = 0; mt < 2; ++mt)
#pragma unroll
                for (int p = 0; p < 4; ++p) {
                    HMMA16(acc[mt][2*p][0],   acc[mt][2*p][1],
                           a[mt][0], a[mt][1], a[mt][2], a[mt][3],
                           bb[p][0], bb[p][1]);
                    HMMA16(acc[mt][2*p+1][0], acc[mt][2*p+1][1],
                           a[mt][0], a[mt][1], a[mt][2], a[mt][3],
                           bb[p][2], bb[p][3]);
                }
        }
        __syncthreads();
    }

    // stage scores (fp16-acc fragments are half2) + both sq vectors
#pragma unroll
    for (int mt = 0; mt < 2; ++mt) {
        const int r0 = wm * 32 + mt * 16 + grp;
        const int cp = wn * 32 + tig;
#pragma unroll
        for (int nt = 0; nt < 8; ++nt) {
            Scw[r0 * SCH2 + cp + nt * 4]       = acc[mt][nt][0];
            Scw[(r0 + 8) * SCH2 + cp + nt * 4] = acc[mt][nt][1];
        }
    }
    if (tid < TILE)      sqi[tid]        = g_sq[b * NN + i0 + tid];
    else                 sqj[tid - 128]  = g_sq[b * NN + j0 + tid - 128];
    __syncthreads();

    float ts[KB];
    int   ti[KB];

    // ---- row-side scan: node = i0+srow, candidates j in stripe jt ----
    {
        const int srow  = tid >> 1;
        const int shalf = tid & 1;
        const int ig    = i0 + srow;
#pragma unroll
        for (int k = 0; k < KB; ++k) { ts[k] = 3.0e38f; ti[k] = 0; }
        const __half2* srcrow = (const __half2*)Scw + srow * SCH2 + shalf * 32;
        const float*   sqrow  = sqj + shalf * 64;
        const int jbase = j0 + shalf * 64;
#pragma unroll 4
        for (int s = 0; s < 32; ++s) {
            float2 v = __half22float2(srcrow[s]);
            int je = jbase + 2 * s;
            float key0 = sqrow[2 * s]     - 2.0f * v.x;
            float key1 = sqrow[2 * s + 1] - 2.0f * v.y;
            if (je != ig)     LIST_INSERT(ts, ti, key0, je);
            if (je + 1 != ig) LIST_INSERT(ts, ti, key1, je + 1);
        }
        size_t base = ((size_t)(b * NN + ig) * NSLOT + (jt * 2 + shalf)) * KB;
#pragma unroll
        for (int k = 0; k < KB; ++k) g_ps[base + k] = packkey(ts[k], ti[k]);
    }

    // ---- col-side scan: node = j0+c, candidates i in stripe it ----
    if (it != jt) {
        const int c  = tid >> 1;
        const int hh = tid & 1;
        const int sel = c & 1;
        const int wofs = c >> 1;
#pragma unroll
        for (int k = 0; k < KB; ++k) { ts[k] = 3.0e38f; ti[k] = 0; }
#pragma unroll 4
        for (int r = 0; r < 64; ++r) {
            const int row = hh * 64 + r;
            uint32_t wdd = Scw[row * SCH2 + wofs];
            __half2 hv = *(__half2*)&wdd;
            float d = sel ? __high2float(hv) : __low2float(hv);
            float key = sqi[row] - 2.0f * d;
            LIST_INSERT(ts, ti, key, i0 + row);
        }
        size_t base = ((size_t)(b * NN + j0 + c) * NSLOT + (it * 2 + hh)) * KB;
#pragma unroll
        for (int k = 0; k < KB; ++k) g_ps[base + k] = packkey(ts[k], ti[k]);
    }
}

// ---------------------------------------------------------------------------
// Kernel 4: merge 432 packed candidates -> top-24 by filter score,
// exact fp32 rescore -> top-8, aggregation + residual + LayerNorm.
// 256 threads = 8 warps, one node per warp.
// ---------------------------------------------------------------------------
__global__ __launch_bounds__(256) void k_refine(const float* __restrict__ gamma,
                                                const float* __restrict__ beta,
                                                float* __restrict__ out) {
    const int b    = blockIdx.y;
    const int wid  = threadIdx.x >> 5;
    const int lane = threadIdx.x & 31;
    const int n0   = blockIdx.x * 8;
    const int n    = n0 + wid;
    const int h = n / WW, w = n % WW;
    const float* Nb = g_nodesT + (size_t)b * NN * CC;

    const float* xi = Nb + (size_t)n * CC + lane * 8;
    float4 x0 = *(const float4*)xi;
    float4 x1 = *(const float4*)(xi + 4);

    // ---- load this node's 432 packed candidates (coalesced via smem) ----
    __shared__ uint32_t stage[8][448];
    {
        size_t base = (size_t)(b * NN + n) * NLIST;
#pragma unroll
        for (int k = 0; k < 14; ++k) {
            int e = lane + k * 32;
            stage[wid][e] = (e < NLIST) ? g_ps[base + e] : 0xFFFFFFFFu;
        }
    }
    __syncwarp();

    // ---- select NCAND smallest packed words (destructive warp-min) ----
    uint32_t r[14];
#pragma unroll
    for (int k = 0; k < 14; ++k) r[k] = stage[wid][lane * 14 + k];
    uint32_t cword = 0xFFFFFFFFu;
    for (int t = 0; t < NCAND; ++t) {
        uint32_t lm = r[0];
#pragma unroll
        for (int k = 1; k < 14; ++k) lm = min(lm, r[k]);
        uint32_t wmv = lm;
#pragma unroll
        for (int o = 16; o > 0; o >>= 1)
            wmv = min(wmv, __shfl_xor_sync(0xffffffffu, wmv, o));
        unsigned msk = __ballot_sync(0xffffffffu, lm == wmv);
        int src = __ffs(msk) - 1;
        if (lane == t) cword = wmv;
        if (lane == src) {
            bool done = false;
#pragma unroll
            for (int k = 0; k < 14; ++k)
                if (!done && r[k] == wmv) { r[k] = 0xFFFFFFFFu; done = true; }
        }
    }
    int cand = (int)(cword & 0xFFFFu);

    // ---- exact rescore of NCAND candidates, 4 at a time ----
    float mykey = 3.0e38f;
    int   myidx = cand;
#pragma unroll
    for (int k0 = 0; k0 < NCAND; k0 += 4) {
        int j0i = __shfl_sync(0xffffffffu, cand, k0);
        int j1i = __shfl_sync(0xffffffffu, cand, k0 + 1);
        int j2i = __shfl_sync(0xffffffffu, cand, k0 + 2);
        int j3i = __shfl_sync(0xffffffffu, cand, k0 + 3);
        const float* r0p = Nb + (size_t)j0i * CC + lane * 8;
        const float* r1p = Nb + (size_t)j1i * CC + lane * 8;
        const float* r2p = Nb + (size_t)j2i * CC + lane * 8;
        const float* r3p = Nb + (size_t)j3i * CC + lane * 8;
        float4 a0 = *(const float4*)r0p, a1 = *(const float4*)(r0p + 4);
        float4 b0 = *(const float4*)r1p, b1 = *(const float4*)(r1p + 4);
        float4 c0 = *(const float4*)r2p, c1 = *(const float4*)(r2p + 4);
        float4 d0 = *(const float4*)r3p, d1 = *(const float4*)(r3p + 4);
        float p0 = x0.x*a0.x + x0.y*a0.y + x0.z*a0.z + x0.w*a0.w
                 + x1.x*a1.x + x1.y*a1.y + x1.z*a1.z + x1.w*a1.w;
        float p1 = x0.x*b0.x + x0.y*b0.y + x0.z*b0.z + x0.w*b0.w
                 + x1.x*b1.x + x1.y*b1.y + x1.z*b1.z + x1.w*b1.w;
        float p2 = x0.x*c0.x + x0.y*c0.y + x0.z*c0.z + x0.w*c0.w
                 + x1.x*c1.x + x1.y*c1.y + x1.z*c1.z + x1.w*c1.w;
        float p3 = x0.x*d0.x + x0.y*d0.y + x0.z*d0.z + x0.w*d0.w
                 + x1.x*d1.x + x1.y*d1.y + x1.z*d1.z + x1.w*d1.w;
#pragma unroll
        for (int o = 16; o > 0; o >>= 1) {
            p0 += __shfl_xor_sync(0xffffffffu, p0, o);
            p1 += __shfl_xor_sync(0xffffffffu, p1, o);
            p2 += __shfl_xor_sync(0xffffffffu, p2, o);
            p3 += __shfl_xor_sync(0xffffffffu, p3, o);
        }
        if (lane == k0)     mykey = g_sq[b * NN + j0i] - 2.0f * p0;
        if (lane == k0 + 1) mykey = g_sq[b * NN + j1i] - 2.0f * p1;
        if (lane == k0 + 2) mykey = g_sq[b * NN + j2i] - 2.0f * p2;
        if (lane == k0 + 3) mykey = g_sq[b * NN + j3i] - 2.0f * p3;
    }

    // ---- select 8 smallest; indices broadcast to all lanes ----
    int knn_j[KNN];
#pragma unroll
    for (int t = 0; t < KNN; ++t) {
        float v = mykey;
#pragma unroll
        for (int o = 16; o > 0; o >>= 1) v = fminf(v, __shfl_xor_sync(0xffffffffu, v, o));
        unsigned m = __ballot_sync(0xffffffffu, mykey == v);
        int src = __ffs(m) - 1;
        knn_j[t] = __shfl_sync(0xffffffffu, myidx, src);
        if (lane == src) mykey = 3.0e38f;
    }

    // ---- aggregate: 4-neighborhood grid + 8 knn, mean; residual ----
    float acc[8];
#pragma unroll
    for (int r2 = 0; r2 < 8; ++r2) acc[r2] = 0.f;
    int cnt = KNN;
#pragma unroll
    for (int t = 0; t < KNN; ++t) {
        const float* p = Nb + (size_t)knn_j[t] * CC + lane * 8;
        float4 y0 = *(const float4*)p;
        float4 y1 = *(const float4*)(p + 4);
        acc[0] += y0.x; acc[1] += y0.y; acc[2] += y0.z; acc[3] += y0.w;
        acc[4] += y1.x; acc[5] += y1.y; acc[6] += y1.z; acc[7] += y1.w;
    }
    if (w > 0)      { const float* p = Nb + (size_t)(n - 1)  * CC + lane * 8;
        float4 y0 = *(const float4*)p; float4 y1 = *(const float4*)(p + 4);
        acc[0]+=y0.x; acc[1]+=y0.y; acc[2]+=y0.z; acc[3]+=y0.w;
        acc[4]+=y1.x; acc[5]+=y1.y; acc[6]+=y1.z; acc[7]+=y1.w; cnt++; }
    if (w < WW - 1) { const float* p = Nb + (size_t)(n + 1)  * CC + lane * 8;
        float4 y0 = *(const float4*)p; float4 y1 = *(const float4*)(p + 4);
        acc[0]+=y0.x; acc[1]+=y0.y; acc[2]+=y0.z; acc[3]+=y0.w;
        acc[4]+=y1.x; acc[5]+=y1.y; acc[6]+=y1.z; acc[7]+=y1.w; cnt++; }
    if (h > 0)      { const float* p = Nb + (size_t)(n - WW) * CC + lane * 8;
        float4 y0 = *(const float4*)p; float4 y1 = *(const float4*)(p + 4);
        acc[0]+=y0.x; acc[1]+=y0.y; acc[2]+=y0.z; acc[3]+=y0.w;
        acc[4]+=y1.x; acc[5]+=y1.y; acc[6]+=y1.z; acc[7]+=y1.w; cnt++; }
    if (h < HH - 1) { const float* p = Nb + (size_t)(n + WW) * CC + lane * 8;
        float4 y0 = *(const float4*)p; float4 y1 = *(const float4*)(p + 4);
        acc[0]+=y0.x; acc[1]+=y0.y; acc[2]+=y0.z; acc[3]+=y0.w;
        acc[4]+=y1.x; acc[5]+=y1.y; acc[6]+=y1.z; acc[7]+=y1.w; cnt++; }

    const float inv = 1.0f / (float)cnt;
    float xv[8] = {x0.x, x0.y, x0.z, x0.w, x1.x, x1.y, x1.z, x1.w};
    float y[8];
#pragma unroll
    for (int r2 = 0; r2 < 8; ++r2) y[r2] = acc[r2] * inv + xv[r2];

    // ---- LayerNorm over channels ----
    float s = 0.f;
#pragma unroll
    for (int r2 = 0; r2 < 8; ++r2) s += y[r2];
#pragma unroll
    for (int o = 16; o > 0; o >>= 1) s += __shfl_xor_sync(0xffffffffu, s, o);
    const float mu = s * (1.0f / CC);
    float v = 0.f;
#pragma unroll
    for (int r2 = 0; r2 < 8; ++r2) { float d = y[r2] - mu; v += d * d; }
#pragma unroll
    for (int o = 16; o > 0; o >>= 1) v += __shfl_xor_sync(0xffffffffu, v, o);
    const float rs = rsqrtf(v * (1.0f / CC) + 1e-5f);

    __shared__ float st[8][CC];
#pragma unroll
    for (int r2 = 0; r2 < 8; ++r2) {
        int c = lane * 8 + r2;
        st[wid][c] = (y[r2] - mu) * rs * gamma[c] + beta[c];
    }
    __syncthreads();

    const int c = threadIdx.x;
    float4 v0 = make_float4(st[0][c], st[1][c], st[2][c], st[3][c]);
    float4 v1 = make_float4(st[4][c], st[5][c], st[6][c], st[7][c]);
    size_t o = (size_t)b * CC * NN + (size_t)c * NN + n0;
    *(float4*)&out[o]     = v0;
    *(float4*)&out[o + 4] = v1;
}

// ---------------------------------------------------------------------------
extern "C" void kernel_launch(void* const* d_in, const int* in_sizes, int n_in,
                              void* d_out, int out_size) {
    const float* F     = (const float*)d_in[0];
    const float* gamma = (const float*)d_in[1];
    const float* beta  = (const float*)d_in[2];
    float* out = (float*)d_out;
    (void)in_sizes; (void)n_in; (void)out_size;

    k_transpose<<<dim3(NN / 32, CC / 32, BQ), dim3(32, 8)>>>(F);
    k_sq<<<dim3(NN / 8, BQ), 256>>>();

    cudaFuncSetAttribute(k_gram_sym,
                         cudaFuncAttributeMaxDynamicSharedMemorySize, SMB_TOT);
    k_gram_sym<<<dim3(NPAIR, BQ), 256, SMB_TOT>>>();

    k_refine<<<dim3(NN / 8, BQ), 256>>>(gamma, beta, out);
}

// round 10
// speedup vs baseline: 1.2326x; 1.2125x over previous
#include <cuda_runtime.h>
#include <cuda_fp16.h>
#include <cstdint>

// Problem constants (fixed shapes)
#define BQ  16
#define CC  256
#define HH  48
#define WW  48
#define NN  (HH*WW)      // 2304
#define KNN 8
#define KB  12           // per-tile candidate list length (sorted, best-first)
#define NSLOT 18         // one list per tile stripe
#define NLIST (NSLOT*KB) // 216 packed candidates per node
#define NCAND 16         // merged candidates that get exact rescore
#define TILE 128
#define NTILES (NN/TILE) // 18
#define NPAIR  171       // NTILES*(NTILES+1)/2

// gram smem layout (bytes); fp16 chunk row = 64 fp16 (128B) + 16 pad = 144
#define CRW    144
#define SMB_A0 0                   // also reused as merge buffer after MMA
#define SMB_A1 18432
#define SMB_B0 36864
#define SMB_B1 55296
#define SMB_SC 73728               // half2[128][65] = 33280
#define SCH2   65
#define SMB_SQI 107008             // float[128]
#define SMB_SQJ 107520             // float[128]
#define SMB_TOT 108032

// Scratch (device globals; no allocation allowed)
__device__ __align__(256) float    g_nodesT[BQ * NN * CC];  // fp32 features [B][N][C]
__device__ __align__(256) __half   g_half[BQ * NN * CC];    // fp16 copy for filter GEMM
__device__ __align__(256) float    g_sq[BQ * NN];           // squared norms
__device__ __align__(256) uint32_t g_ps[(size_t)BQ * NN * NLIST]; // packed cand lists

__device__ __forceinline__ uint32_t smem_u32(const void* p) {
    uint32_t a;
    asm("{ .reg .u64 t; cvta.to.shared.u64 t, %1; cvt.u32.u64 %0, t; }"
        : "=r"(a) : "l"(p));
    return a;
}
#define CP_ASYNC16(dst, src) \
    asm volatile("cp.async.cg.shared.global [%0], [%1], 16;" :: "r"(dst), "l"(src))
#define CP_COMMIT() asm volatile("cp.async.commit_group;" ::: "memory")
#define CP_WAIT(n)  asm volatile("cp.async.wait_group %0;" :: "n"(n) : "memory")

#define LDSM_X4(r0, r1, r2, r3, addr) \
    asm volatile("ldmatrix.sync.aligned.m8n8.x4.shared.b16 {%0,%1,%2,%3}, [%4];" \
        : "=r"(r0), "=r"(r1), "=r"(r2), "=r"(r3) : "r"(addr))

#define HMMA16(acc0, acc1, a0, a1, a2, a3, b0, b1) \
    asm volatile("mma.sync.aligned.m16n8k16.row.col.f16.f16.f16.f16 " \
        "{%0,%1}, {%2,%3,%4,%5}, {%6,%7}, {%0,%1};" \
        : "+r"(acc0), "+r"(acc1) \
        : "r"(a0), "r"(a1), "r"(a2), "r"(a3), "r"(b0), "r"(b1))

// pack fp32 key -> monotone fp16 bits (hi) | node idx (lo); uint32 asc == key asc
__device__ __forceinline__ uint32_t packkey(float key, int idx) {
    unsigned short h = __half_as_ushort(__float2half_rn(key));
    h = (unsigned short)(h ^ ((h & 0x8000) ? 0xFFFFu : 0x8000u));
    return ((uint32_t)h << 16) | (uint32_t)(idx & 0xFFFF);
}

// insertion update for a top-KB list, [0]=worst
#define LIST_INSERT(ts, ti, key, idx) do { \
    if ((key) < (ts)[0]) { \
        (ts)[0] = (key); (ti)[0] = (idx); \
        _Pragma("unroll") \
        for (int _t = 0; _t < KB - 1; ++_t) \
            if ((ts)[_t] < (ts)[_t + 1]) { \
                float _f = (ts)[_t]; (ts)[_t] = (ts)[_t+1]; (ts)[_t+1] = _f; \
                int _n = (ti)[_t]; (ti)[_t] = (ti)[_t+1]; (ti)[_t+1] = _n; \
            } \
    } \
} while (0)

// ---------------------------------------------------------------------------
// Kernel 1: transpose F[b][c][n] -> nodesT[b][n][c] (fp32 + fp16 copies)
// ---------------------------------------------------------------------------
__global__ void k_transpose(const float* __restrict__ F) {
    __shared__ float t[32][33];
    int b  = blockIdx.z;
    int n0 = blockIdx.x * 32;
    int c0 = blockIdx.y * 32;
    const float* Fb = F + (size_t)b * CC * NN;
    int tx = threadIdx.x, ty = threadIdx.y;  // 32 x 8
#pragma unroll
    for (int i = 0; i < 32; i += 8)
        t[ty + i][tx] = Fb[(size_t)(c0 + ty + i) * NN + n0 + tx];
    __syncthreads();
    float* out = g_nodesT + (size_t)b * NN * CC;
    __half* outh = g_half + (size_t)b * NN * CC;
#pragma unroll
    for (int i = 0; i < 32; i += 8) {
        float v = t[tx][ty + i];
        size_t o = (size_t)(n0 + ty + i) * CC + c0 + tx;
        out[o]  = v;
        outh[o] = __float2half(v);
    }
}

// ---------------------------------------------------------------------------
// Kernel 2: squared norms from g_nodesT (coalesced; warp per node)
// ---------------------------------------------------------------------------
__global__ void k_sq() {
    const int wid  = threadIdx.x >> 5;
    const int lane = threadIdx.x & 31;
    const int n = blockIdx.x * 8 + wid;
    const int b = blockIdx.y;
    const float* p = g_nodesT + (size_t)(b * NN + n) * CC + lane * 8;
    float4 a = *(const float4*)p;
    float4 c = *(const float4*)(p + 4);
    float s = a.x*a.x + a.y*a.y + a.z*a.z + a.w*a.w
            + c.x*c.x + c.y*c.y + c.z*c.z + c.w*c.w;
#pragma unroll
    for (int o = 16; o > 0; o >>= 1) s += __shfl_xor_sync(0xffffffffu, s, o);
    if (lane == 0) g_sq[b * NN + n] = s;
}

// ---------------------------------------------------------------------------
// Kernel 3: symmetric fp16 Gram — one CTA per tile-pair (it <= jt).
// MMA core = R7 (fp16 in/acc, cp.async double-buffered, ldmatrix).
// Row scan -> per-half top-12, pair-merged in smem -> sorted best-first
// 12-list for stripe-it nodes (slot jt). Col scan -> same for stripe-jt
// nodes (slot it; skipped on diagonal). Each (node, slot) written once.
// ---------------------------------------------------------------------------
__global__ __launch_bounds__(256, 2) void k_gram_sym() {
    extern __shared__ unsigned char smraw[];
    const uint32_t smb = smem_u32(smraw);
    uint32_t* Scw = (uint32_t*)(smraw + SMB_SC);  // half2[128][65]
    float*    sqi = (float*)(smraw + SMB_SQI);
    float*    sqj = (float*)(smraw + SMB_SQJ);
    uint32_t (*mbuf)[KB] = (uint32_t (*)[KB])(smraw + SMB_A0);  // [256][12]

    const int b = blockIdx.y;
    // map linear pair index -> (it, jt), it <= jt
    int tlin = blockIdx.x, it = 0;
    while (tlin >= NTILES - it) { tlin -= NTILES - it; ++it; }
    const int jt = it + tlin;
    const int i0 = it * TILE, j0 = jt * TILE;

    const int tid = threadIdx.x;
    const int wid  = tid >> 5;
    const int lane = tid & 31;
    const int wm = wid >> 1;       // 0..3
    const int wn = wid & 1;        // 0..1
    const int grp = lane >> 2;     // 0..7
    const int tig = lane & 3;      // 0..3
    const int quad = lane >> 3;    // 0..3
    const int wi   = lane & 7;
    const __half* Hb = g_half + (size_t)b * NN * CC;

    // chunk copy geometry: 2 threads per row, 64B halves
    const int crow  = tid >> 1;
    const int chalf = tid & 1;

    // ldmatrix per-lane offsets (within a chunk buffer)
    uint32_t aoff[2], boff[4];
#pragma unroll
    for (int mt = 0; mt < 2; ++mt) {
        int row = wm * 32 + mt * 16 + wi + 8 * (quad & 1);
        aoff[mt] = row * CRW + (quad >> 1) * 16;
    }
#pragma unroll
    for (int p = 0; p < 4; ++p) {
        int row = wn * 64 + p * 16 + wi + 8 * (quad >> 1);
        boff[p] = row * CRW + (quad & 1) * 16;
    }

    // issue chunk q (A from stripe it, B from stripe jt -> buffer q&1)
    auto issue = [&](int q) {
        const int c = q, buf = q & 1;
        const char* asrc =
            (const char*)(Hb + (size_t)(i0 + crow) * CC + c * 64 + chalf * 32);
        const char* bsrc =
            (const char*)(Hb + (size_t)(j0 + crow) * CC + c * 64 + chalf * 32);
        uint32_t adst = smb + (buf ? SMB_A1 : SMB_A0) + crow * CRW + chalf * 64;
        uint32_t bdst = smb + (buf ? SMB_B1 : SMB_B0) + crow * CRW + chalf * 64;
#pragma unroll
        for (int i = 0; i < 4; ++i) {
            CP_ASYNC16(adst + i * 16, asrc + i * 16);
            CP_ASYNC16(bdst + i * 16, bsrc + i * 16);
        }
        CP_COMMIT();
    };

    issue(0);

    uint32_t acc[2][8][2];
#pragma unroll
    for (int mt = 0; mt < 2; ++mt)
#pragma unroll
        for (int nt = 0; nt < 8; ++nt)
            acc[mt][nt][0] = acc[mt][nt][1] = 0u;

    for (int q = 0; q < 4; ++q) {
        if (q + 1 < 4) { issue(q + 1); CP_WAIT(1); }
        else           {               CP_WAIT(0); }
        __syncthreads();

        const uint32_t abase = smb + ((q & 1) ? SMB_A1 : SMB_A0);
        const uint32_t bbase = smb + ((q & 1) ? SMB_B1 : SMB_B0);
#pragma unroll
        for (int ks = 0; ks < 4; ++ks) {
            const int ko = ks * 32;
            uint32_t a[2][4];
#pragma unroll
            for (int mt = 0; mt < 2; ++mt)
                LDSM_X4(a[mt][0], a[mt][1], a[mt][2], a[mt][3],
                        abase + aoff[mt] + ko);
            uint32_t bb[4][4];
#pragma unroll
            for (int p = 0; p < 4; ++p)
                LDSM_X4(bb[p][0], bb[p][1], bb[p][2], bb[p][3],
                        bbase + boff[p] + ko);
#pragma unroll
            for (int mt = 0; mt < 2; ++mt)
#pragma unroll
                for (int p = 0; p < 4; ++p) {
                    HMMA16(acc[mt][2*p][0],   acc[mt][2*p][1],
                           a[mt][0], a[mt][1], a[mt][2], a[mt][3],
                           bb[p][0], bb[p][1]);
                    HMMA16(acc[mt][2*p+1][0], acc[mt][2*p+1][1],
                           a[mt][0], a[mt][1], a[mt][2], a[mt][3],
                           bb[p][2], bb[p][3]);
                }
        }
        __syncthreads();
    }

    // stage scores (fp16-acc fragments are half2) + both sq vectors
#pragma unroll
    for (int mt = 0; mt < 2; ++mt) {
        const int r0 = wm * 32 + mt * 16 + grp;
        const int cp = wn * 32 + tig;
#pragma unroll
        for (int nt = 0; nt < 8; ++nt) {
            Scw[r0 * SCH2 + cp + nt * 4]       = acc[mt][nt][0];
            Scw[(r0 + 8) * SCH2 + cp + nt * 4] = acc[mt][nt][1];
        }
    }
    if (tid < TILE)      sqi[tid]        = g_sq[b * NN + i0 + tid];
    else                 sqj[tid - 128]  = g_sq[b * NN + j0 + tid - 128];
    __syncthreads();

    float ts[KB];
    int   ti[KB];

    // ---- row-side scan: node = i0+srow; halves merged -> slot jt ----
    {
        const int srow  = tid >> 1;
        const int shalf = tid & 1;
        const int ig    = i0 + srow;
#pragma unroll
        for (int k = 0; k < KB; ++k) { ts[k] = 3.0e38f; ti[k] = 0; }
        const __half2* srcrow = (const __half2*)Scw + srow * SCH2 + shalf * 32;
        const float*   sqrow  = sqj + shalf * 64;
        const int jbase = j0 + shalf * 64;
#pragma unroll 4
        for (int s = 0; s < 32; ++s) {
            float2 v = __half22float2(srcrow[s]);
            int je = jbase + 2 * s;
            float key0 = sqrow[2 * s]     - 2.0f * v.x;
            float key1 = sqrow[2 * s + 1] - 2.0f * v.y;
            if (je != ig)     LIST_INSERT(ts, ti, key0, je);
            if (je + 1 != ig) LIST_INSERT(ts, ti, key1, je + 1);
        }
        // pack (descending: [0]=worst) into merge buffer
#pragma unroll
        for (int k = 0; k < KB; ++k) mbuf[tid][k] = packkey(ts[k], ti[k]);
        __syncwarp();
        if (shalf == 0) {
            // 2-pointer merge of two descending lists, take 12 best ascending
            int ia = KB - 1, ib = KB - 1;
            size_t base = ((size_t)(b * NN + ig) * NSLOT + jt) * KB;
#pragma unroll
            for (int t = 0; t < KB; ++t) {
                uint32_t va = mbuf[tid][ia], vb = mbuf[tid + 1][ib];
                if (va < vb) { g_ps[base + t] = va; --ia; }
                else         { g_ps[base + t] = vb; --ib; }
            }
        }
        __syncwarp();
    }

    // ---- col-side scan: node = j0+c; halves merged -> slot it ----
    if (it != jt) {
        const int c  = tid >> 1;
        const int hh = tid & 1;
        const int sel = c & 1;
        const int wofs = c >> 1;
#pragma unroll
        for (int k = 0; k < KB; ++k) { ts[k] = 3.0e38f; ti[k] = 0; }
#pragma unroll 4
        for (int r = 0; r < 64; ++r) {
            const int row = hh * 64 + r;
            uint32_t wdd = Scw[row * SCH2 + wofs];
            __half2 hv = *(__half2*)&wdd;
            float d = sel ? __high2float(hv) : __low2float(hv);
            float key = sqi[row] - 2.0f * d;
            LIST_INSERT(ts, ti, key, i0 + row);
        }
#pragma unroll
        for (int k = 0; k < KB; ++k) mbuf[tid][k] = packkey(ts[k], ti[k]);
        __syncwarp();
        if (hh == 0) {
            int ia = KB - 1, ib = KB - 1;
            size_t base = ((size_t)(b * NN + j0 + c) * NSLOT + it) * KB;
#pragma unroll
            for (int t = 0; t < KB; ++t) {
                uint32_t va = mbuf[tid][ia], vb = mbuf[tid + 1][ib];
                if (va < vb) { g_ps[base + t] = va; --ia; }
                else         { g_ps[base + t] = vb; --ib; }
            }
        }
    }
}

// ---------------------------------------------------------------------------
// Kernel 4: tournament-merge 18 sorted lists -> top-16 by filter score,
// exact fp32 rescore -> top-8, aggregation + residual + LayerNorm.
// 256 threads = 8 warps, one node per warp.
// ---------------------------------------------------------------------------
__global__ __launch_bounds__(256) void k_refine(const float* __restrict__ gamma,
                                                const float* __restrict__ beta,
                                                float* __restrict__ out) {
    const int b    = blockIdx.y;
    const int wid  = threadIdx.x >> 5;
    const int lane = threadIdx.x & 31;
    const int n0   = blockIdx.x * 8;
    const int n    = n0 + wid;
    const int h = n / WW, w = n % WW;
    const float* Nb = g_nodesT + (size_t)b * NN * CC;

    const float* xi = Nb + (size_t)n * CC + lane * 8;
    float4 x0 = *(const float4*)xi;
    float4 x1 = *(const float4*)(xi + 4);

    // ---- load this node's 216 packed candidates (coalesced via smem) ----
    __shared__ uint32_t stage[8][224];
    {
        size_t base = (size_t)(b * NN + n) * NLIST;
#pragma unroll
        for (int k = 0; k < 7; ++k) {
            int e = lane + k * 32;
            stage[wid][e] = (e < NLIST) ? g_ps[base + e] : 0xFFFFFFFFu;
        }
    }
    __syncwarp();

    // ---- tournament: lane l < NSLOT owns sorted list l (best-first) ----
    uint32_t head = 0xFFFFFFFFu;
    int hp = 0;
    if (lane < NSLOT) head = stage[wid][lane * KB];
    uint32_t cword = 0xFFFFFFFFu;
#pragma unroll
    for (int t = 0; t < NCAND; ++t) {
        uint32_t wmv = __reduce_min_sync(0xffffffffu, head);
        if (lane == t) cword = wmv;
        unsigned msk = __ballot_sync(0xffffffffu, head == wmv);
        if (lane == (__ffs(msk) - 1)) {
            ++hp;
            head = (hp < KB) ? stage[wid][lane * KB + hp] : 0xFFFFFFFFu;
        }
    }
    int cand = (int)(cword & 0xFFFFu);

    // ---- exact rescore of NCAND candidates, 4 at a time ----
    float mykey = 3.0e38f;
    int   myidx = cand;
#pragma unroll
    for (int k0 = 0; k0 < NCAND; k0 += 4) {
        int j0i = __shfl_sync(0xffffffffu, cand, k0);
        int j1i = __shfl_sync(0xffffffffu, cand, k0 + 1);
        int j2i = __shfl_sync(0xffffffffu, cand, k0 + 2);
        int j3i = __shfl_sync(0xffffffffu, cand, k0 + 3);
        const float* r0p = Nb + (size_t)j0i * CC + lane * 8;
        const float* r1p = Nb + (size_t)j1i * CC + lane * 8;
        const float* r2p = Nb + (size_t)j2i * CC + lane * 8;
        const float* r3p = Nb + (size_t)j3i * CC + lane * 8;
        float4 a0 = *(const float4*)r0p, a1 = *(const float4*)(r0p + 4);
        float4 b0 = *(const float4*)r1p, b1 = *(const float4*)(r1p + 4);
        float4 c0 = *(const float4*)r2p, c1 = *(const float4*)(r2p + 4);
        float4 d0 = *(const float4*)r3p, d1 = *(const float4*)(r3p + 4);
        float p0 = x0.x*a0.x + x0.y*a0.y + x0.z*a0.z + x0.w*a0.w
                 + x1.x*a1.x + x1.y*a1.y + x1.z*a1.z + x1.w*a1.w;
        float p1 = x0.x*b0.x + x0.y*b0.y + x0.z*b0.z + x0.w*b0.w
                 + x1.x*b1.x + x1.y*b1.y + x1.z*b1.z + x1.w*b1.w;
        float p2 = x0.x*c0.x + x0.y*c0.y + x0.z*c0.z + x0.w*c0.w
                 + x1.x*c1.x + x1.y*c1.y + x1.z*c1.z + x1.w*c1.w;
        float p3 = x0.x*d0.x + x0.y*d0.y + x0.z*d0.z + x0.w*d0.w
                 + x1.x*d1.x + x1.y*d1.y + x1.z*d1.z + x1.w*d1.w;
#pragma unroll
        for (int o = 16; o > 0; o >>= 1) {
            p0 += __shfl_xor_sync(0xffffffffu, p0, o);
            p1 += __shfl_xor_sync(0xffffffffu, p1, o);
            p2 += __shfl_xor_sync(0xffffffffu, p2, o);
            p3 += __shfl_xor_sync(0xffffffffu, p3, o);
        }
        if (lane == k0)     mykey = g_sq[b * NN + j0i] - 2.0f * p0;
        if (lane == k0 + 1) mykey = g_sq[b * NN + j1i] - 2.0f * p1;
        if (lane == k0 + 2) mykey = g_sq[b * NN + j2i] - 2.0f * p2;
        if (lane == k0 + 3) mykey = g_sq[b * NN + j3i] - 2.0f * p3;
    }

    // ---- select 8 smallest; indices broadcast to all lanes ----
    int knn_j[KNN];
#pragma unroll
    for (int t = 0; t < KNN; ++t) {
        float v = mykey;
#pragma unroll
        for (int o = 16; o > 0; o >>= 1) v = fminf(v, __shfl_xor_sync(0xffffffffu, v, o));
        unsigned m = __ballot_sync(0xffffffffu, mykey == v);
        int src = __ffs(m) - 1;
        knn_j[t] = __shfl_sync(0xffffffffu, myidx, src);
        if (lane == src) mykey = 3.0e38f;
    }

    // ---- aggregate: 4-neighborhood grid + 8 knn, mean; residual ----
    float acc[8];
#pragma unroll
    for (int r2 = 0; r2 < 8; ++r2) acc[r2] = 0.f;
    int cnt = KNN;
#pragma unroll
    for (int t = 0; t < KNN; ++t) {
        const float* p = Nb + (size_t)knn_j[t] * CC + lane * 8;
        float4 y0 = *(const float4*)p;
        float4 y1 = *(const float4*)(p + 4);
        acc[0] += y0.x; acc[1] += y0.y; acc[2] += y0.z; acc[3] += y0.w;
        acc[4] += y1.x; acc[5] += y1.y; acc[6] += y1.z; acc[7] += y1.w;
    }
    if (w > 0)      { const float* p = Nb + (size_t)(n - 1)  * CC + lane * 8;
        float4 y0 = *(const float4*)p; float4 y1 = *(const float4*)(p + 4);
        acc[0]+=y0.x; acc[1]+=y0.y; acc[2]+=y0.z; acc[3]+=y0.w;
        acc[4]+=y1.x; acc[5]+=y1.y; acc[6]+=y1.z; acc[7]+=y1.w; cnt++; }
    if (w < WW - 1) { const float* p = Nb + (size_t)(n + 1)  * CC + lane * 8;
        float4 y0 = *(const float4*)p; float4 y1 = *(const float4*)(p + 4);
        acc[0]+=y0.x; acc[1]+=y0.y; acc[2]+=y0.z; acc[3]+=y0.w;
        acc[4]+=y1.x; acc[5]+=y1.y; acc[6]+=y1.z; acc[7]+=y1.w; cnt++; }
    if (h > 0)      { const float* p = Nb + (size_t)(n - WW) * CC + lane * 8;
        float4 y0 = *(const float4*)p; float4 y1 = *(const float4*)(p + 4);
        acc[0]+=y0.x; acc[1]+=y0.y; acc[2]+=y0.z; acc[3]+=y0.w;
        acc[4]+=y1.x; acc[5]+=y1.y; acc[6]+=y1.z; acc[7]+=y1.w; cnt++; }
    if (h < HH - 1) { const float* p = Nb + (size_t)(n + WW) * CC + lane * 8;
        float4 y0 = *(const float4*)p; float4 y1 = *(const float4*)(p + 4);
        acc[0]+=y0.x; acc[1]+=y0.y; acc[2]+=y0.z; acc[3]+=y0.w;
        acc[4]+=y1.x; acc[5]+=y1.y; acc[6]+=y1.z; acc[7]+=y1.w; cnt++; }

    const float inv = 1.0f / (float)cnt;
    float xv[8] = {x0.x, x0.y, x0.z, x0.w, x1.x, x1.y, x1.z, x1.w};
    float y[8];
#pragma unroll
    for (int r2 = 0; r2 < 8; ++r2) y[r2] = acc[r2] * inv + xv[r2];

    // ---- LayerNorm over channels ----
    float s = 0.f;
#pragma unroll
    for (int r2 = 0; r2 < 8; ++r2) s += y[r2];
#pragma unroll
    for (int o = 16; o > 0; o >>= 1) s += __shfl_xor_sync(0xffffffffu, s, o);
    const float mu = s * (1.0f / CC);
    float v = 0.f;
#pragma unroll
    for (int r2 = 0; r2 < 8; ++r2) { float d = y[r2] - mu; v += d * d; }
#pragma unroll
    for (int o = 16; o > 0; o >>= 1) v += __shfl_xor_sync(0xffffffffu, v, o);
    const float rs = rsqrtf(v * (1.0f / CC) + 1e-5f);

    __shared__ float st[8][CC];
#pragma unroll
    for (int r2 = 0; r2 < 8; ++r2) {
        int c = lane * 8 + r2;
        st[wid][c] = (y[r2] - mu) * rs * gamma[c] + beta[c];
    }
    __syncthreads();

    const int c = threadIdx.x;
    float4 v0 = make_float4(st[0][c], st[1][c], st[2][c], st[3][c]);
    float4 v1 = make_float4(st[4][c], st[5][c], st[6][c], st[7][c]);
    size_t o = (size_t)b * CC * NN + (size_t)c * NN + n0;
    *(float4*)&out[o]     = v0;
    *(float4*)&out[o + 4] = v1;
}

// ---------------------------------------------------------------------------
extern "C" void kernel_launch(void* const* d_in, const int* in_sizes, int n_in,
                              void* d_out, int out_size) {
    const float* F     = (const float*)d_in[0];
    const float* gamma = (const float*)d_in[1];
    const float* beta  = (const float*)d_in[2];
    float* out = (float*)d_out;
    (void)in_sizes; (void)n_in; (void)out_size;

    k_transpose<<<dim3(NN / 32, CC / 32, BQ), dim3(32, 8)>>>(F);
    k_sq<<<dim3(NN / 8, BQ), 256>>>();

    cudaFuncSetAttribute(k_gram_sym,
                         cudaFuncAttributeMaxDynamicSharedMemorySize, SMB_TOT);
    k_gram_sym<<<dim3(NPAIR, BQ), 256, SMB_TOT>>>();

    k_refine<<<dim3(NN / 8, BQ), 256>>>(gamma, beta, out);
}